// round 6
// baseline (speedup 1.0000x reference)
#include <cuda_runtime.h>
#include <math.h>

#define NN 50000
#define EE 400000
#define DD 64
#define HH 4
#define CC 64
#define HC 256
#define EDD 16

typedef unsigned long long ull;

// ---------------- static scratch ----------------
__device__ __align__(16) float g_xl[(size_t)NN * HC];
__device__ __align__(16) float g_xr[(size_t)NN * HC];
__device__ __align__(16) float g_mid[(size_t)NN * DD];
__device__ __align__(16) float g_eacsr[(size_t)EE * EDD];
__device__ __align__(16) float g_ex[(size_t)EE * HH];   // exp(alpha) per edge/head
__device__ int g_cnt[NN];
__device__ int g_cursor[NN];
__device__ int g_rowptr[NN + 1];
__device__ int g_esrc[EE];
__device__ int g_edst[EE];
__device__ int g_eord[EE];

// ---------------- packed f32x2 helpers ----------------
__device__ __forceinline__ ull pk2(float a, float b) {
    ull r; asm("mov.b64 %0, {%1, %2};" : "=l"(r) : "f"(a), "f"(b)); return r;
}
__device__ __forceinline__ ull dup2(float a) {
    ull r; asm("mov.b64 %0, {%1, %1};" : "=l"(r) : "f"(a)); return r;
}
__device__ __forceinline__ float2 up2(ull v) {
    float2 r; asm("mov.b64 {%0, %1}, %2;" : "=f"(r.x), "=f"(r.y) : "l"(v)); return r;
}
__device__ __forceinline__ ull fma2(ull a, ull b, ull c) {
    ull d; asm("fma.rn.f32x2 %0, %1, %2, %3;" : "=l"(d) : "l"(a), "l"(b), "l"(c)); return d;
}
__device__ __forceinline__ ull add2(ull a, ull b) {
    ull d; asm("add.rn.f32x2 %0, %1, %2;" : "=l"(d) : "l"(a), "l"(b)); return d;
}

// ---------------- CSR build ----------------
__global__ void zero_cnt_kernel() {
    int i = blockIdx.x * blockDim.x + threadIdx.x;
    if (i < NN) g_cnt[i] = 0;
}

__global__ void hist_kernel(const int* __restrict__ dst) {
    int e = blockIdx.x * blockDim.x + threadIdx.x;
    if (e < EE) atomicAdd(&g_cnt[dst[e]], 1);
}

__global__ __launch_bounds__(1024) void scan_kernel() {
    __shared__ int wsum[32];
    int t = threadIdx.x;
    int lane = t & 31, wid = t >> 5;
    const int PER = 49;
    int base = t * PER;

    int s = 0;
#pragma unroll 7
    for (int i = 0; i < PER; i++) {
        int idx = base + i;
        if (idx < NN) s += g_cnt[idx];
    }
    int ws = s;
#pragma unroll
    for (int off = 1; off < 32; off <<= 1) {
        int v = __shfl_up_sync(0xffffffffu, ws, off);
        if (lane >= off) ws += v;
    }
    if (lane == 31) wsum[wid] = ws;
    __syncthreads();
    if (wid == 0) {
        int v = wsum[lane];
        int iv = v;
#pragma unroll
        for (int off = 1; off < 32; off <<= 1) {
            int u = __shfl_up_sync(0xffffffffu, iv, off);
            if (lane >= off) iv += u;
        }
        wsum[lane] = iv - v;
    }
    __syncthreads();
    int offset = wsum[wid] + (ws - s);

    int run = offset;
#pragma unroll 7
    for (int i = 0; i < PER; i++) {
        int idx = base + i;
        if (idx < NN) {
            int v = g_cnt[idx];
            g_rowptr[idx] = run;
            g_cursor[idx] = run;
            run += v;
        }
    }
    if (t == 1023) g_rowptr[NN] = run;
}

__global__ void scatter_kernel(const int* __restrict__ src, const int* __restrict__ dst) {
    int e = blockIdx.x * blockDim.x + threadIdx.x;
    if (e < EE) {
        int d = dst[e];
        int pos = atomicAdd(&g_cursor[d], 1);
        g_esrc[pos] = src[e];
        g_edst[pos] = d;
        g_eord[pos] = e;
    }
}

__global__ void permute_ea_kernel(const float* __restrict__ ea) {
    int t = blockIdx.x * blockDim.x + threadIdx.x;
    int pos = t >> 2;
    int c4 = t & 3;
    if (pos < EE) {
        int eid = g_eord[pos];
        ((float4*)g_eacsr)[(size_t)pos * 4 + c4] =
            ((const float4*)ea)[(size_t)eid * 4 + c4];
    }
}

// ---------------- node transform: xl = x@Wl+bl, xr = x@Wr+br ----------------
__global__ __launch_bounds__(512) void transform_kernel(
    const float* __restrict__ x,
    const float* __restrict__ Wl, const float* __restrict__ bl,
    const float* __restrict__ Wr, const float* __restrict__ br)
{
    __shared__ __align__(16) float hs[64 * 64];
    const float* xp = x ? x : g_mid;
    int tid = threadIdx.x;
    int j = tid & 255;
    int isR = tid >> 8;
    const float* W = isR ? Wr : Wl;
    float bj = isR ? br[j] : bl[j];
    float* ob = isR ? g_xr : g_xl;
    int n0 = blockIdx.x * 64;

    ull w2[32];
#pragma unroll
    for (int q = 0; q < 32; q++)
        w2[q] = pk2(W[(2 * q) * HC + j], W[(2 * q + 1) * HC + j]);

    const float4* src4 = (const float4*)(xp + (size_t)n0 * DD);
    int limit4 = (NN - n0) * (DD / 4);
    for (int i = tid; i < 1024; i += 512) {
        float4 v = (i < limit4) ? src4[i] : make_float4(0.f, 0.f, 0.f, 0.f);
        ((float4*)hs)[i] = v;
    }
    __syncthreads();

    int nmax = NN - n0; if (nmax > 64) nmax = 64;
    for (int n = 0; n < nmax; n++) {
        const float4* hrow = (const float4*)(hs + n * 64);
        ull a0 = 0, a1 = 0, a2 = 0, a3 = 0;
#pragma unroll
        for (int q = 0; q < 16; q += 2) {
            float4 h0 = hrow[q], h1 = hrow[q + 1];
            a0 = fma2(pk2(h0.x, h0.y), w2[2 * q + 0], a0);
            a1 = fma2(pk2(h0.z, h0.w), w2[2 * q + 1], a1);
            a2 = fma2(pk2(h1.x, h1.y), w2[2 * q + 2], a2);
            a3 = fma2(pk2(h1.z, h1.w), w2[2 * q + 3], a3);
        }
        float2 f0 = up2(a0), f1 = up2(a1), f2 = up2(a2), f3 = up2(a3);
        ob[(size_t)(n0 + n) * HC + j] =
            bj + ((f0.x + f0.y) + (f1.x + f1.y)) + ((f2.x + f2.y) + (f3.x + f3.y));
    }
}

// ---------------- alpha pass: edge-parallel, one warp per edge ----------------
// block = 256 threads = 8 warps; block handles 64 consecutive CSR edges (8/warp).
// lane owns 8 global channels (cb = lane*8), head = lane/8.
// We in smem (16KB), ea staged (4KB). Output g_ex[pos*4+head] = exp(alpha).
__global__ __launch_bounds__(256) void alpha_kernel(
    const float* __restrict__ We, const float* __restrict__ att)
{
    __shared__ __align__(16) float sWe[16 * 256];
    __shared__ __align__(16) float sea[64 * EDD];
    int tid = threadIdx.x;
    int warp = tid >> 5, lane = tid & 31;
    int base = blockIdx.x * 64;

    for (int i = tid; i < 1024; i += 256)
        ((float4*)sWe)[i] = ((const float4*)We)[i];
    {
        const float4* ga = ((const float4*)g_eacsr) + (size_t)base * 4;
        ((float4*)sea)[tid] = ga[tid];  // 64*16/4 = 256 float4 = exactly blockDim
    }
    __syncthreads();

    int cb = lane * 8;
    int head = lane >> 3;
    float4 at0 = *(const float4*)(att + cb);      // att[4][64] flat == channel index
    float4 at1 = *(const float4*)(att + cb + 4);

    int p0 = base + warp * 8;
    // prefetch edge 0
    int s = g_esrc[p0], d = g_edst[p0];
    float4 xla = *(const float4*)(g_xl + (size_t)s * HC + cb);
    float4 xlb = *(const float4*)(g_xl + (size_t)s * HC + cb + 4);
    float4 xra = *(const float4*)(g_xr + (size_t)d * HC + cb);
    float4 xrb = *(const float4*)(g_xr + (size_t)d * HC + cb + 4);

#pragma unroll 1
    for (int i = 0; i < 8; i++) {
        int p = p0 + i;
        float4 nxla = xla, nxlb = xlb, nxra = xra, nxrb = xrb;
        if (i < 7) {
            int s2 = g_esrc[p + 1], d2 = g_edst[p + 1];
            nxla = *(const float4*)(g_xl + (size_t)s2 * HC + cb);
            nxlb = *(const float4*)(g_xl + (size_t)s2 * HC + cb + 4);
            nxra = *(const float4*)(g_xr + (size_t)d2 * HC + cb);
            nxrb = *(const float4*)(g_xr + (size_t)d2 * HC + cb + 4);
        }

        // y = xl + xr, then accumulate ez (channel-pair packed)
        ull y0 = add2(pk2(xla.x, xla.y), pk2(xra.x, xra.y));
        ull y1 = add2(pk2(xla.z, xla.w), pk2(xra.z, xra.w));
        ull y2 = add2(pk2(xlb.x, xlb.y), pk2(xrb.x, xrb.y));
        ull y3 = add2(pk2(xlb.z, xlb.w), pk2(xrb.z, xrb.w));

        const float* eap = sea + (p - base) * EDD;
#pragma unroll
        for (int k = 0; k < EDD; k++) {
            ull ek = dup2(eap[k]);              // uniform-address LDS broadcast
            const ull* wp = (const ull*)(sWe + k * 256 + cb);
            y0 = fma2(wp[0], ek, y0);
            y1 = fma2(wp[1], ek, y1);
            y2 = fma2(wp[2], ek, y2);
            y3 = fma2(wp[3], ek, y3);
        }
        float2 f0 = up2(y0), f1 = up2(y1), f2 = up2(y2), f3 = up2(y3);
        float v0 = fmaxf(f0.x, 0.2f * f0.x);
        float v1 = fmaxf(f0.y, 0.2f * f0.y);
        float v2 = fmaxf(f1.x, 0.2f * f1.x);
        float v3 = fmaxf(f1.y, 0.2f * f1.y);
        float v4 = fmaxf(f2.x, 0.2f * f2.x);
        float v5 = fmaxf(f2.y, 0.2f * f2.y);
        float v6 = fmaxf(f3.x, 0.2f * f3.x);
        float v7 = fmaxf(f3.y, 0.2f * f3.y);
        float ap = v0 * at0.x;
        ap = fmaf(v1, at0.y, ap);
        ap = fmaf(v2, at0.z, ap);
        ap = fmaf(v3, at0.w, ap);
        ap = fmaf(v4, at1.x, ap);
        ap = fmaf(v5, at1.y, ap);
        ap = fmaf(v6, at1.z, ap);
        ap = fmaf(v7, at1.w, ap);
        // reduce over the 8 lanes of this head
        ap += __shfl_xor_sync(0xffffffffu, ap, 1);
        ap += __shfl_xor_sync(0xffffffffu, ap, 2);
        ap += __shfl_xor_sync(0xffffffffu, ap, 4);

        float ex = __expf(ap);  // softmax w/o max-shift: scale-invariant, logits O(+-8)
        if ((lane & 7) == 0) g_ex[(size_t)p * HH + head] = ex;

        xla = nxla; xlb = nxlb; xra = nxra; xrb = nxrb;
    }
}

// ---------------- aggregation: one warp per node (no smem, no syncthreads) -----
// lane owns 8 global channels (cb = lane*8), head = lane/8, wc = cb & 63.
__global__ __launch_bounds__(256) void agg_kernel(
    const float* __restrict__ bias,
    const float* __restrict__ lng, const float* __restrict__ lnb,
    const float* __restrict__ residual,
    float* __restrict__ out_ext, int use_ext)
{
    int n = (blockIdx.x * 256 + threadIdx.x) >> 5;
    int lane = threadIdx.x & 31;
    if (n >= NN) return;
    float* out = use_ext ? out_ext : g_mid;

    int cb = lane * 8;
    int head = lane >> 3;
    int wc = cb & 63;

    int e0 = g_rowptr[n], e1 = g_rowptr[n + 1];
    ull acc0 = 0, acc1 = 0, acc2 = 0, acc3 = 0;
    float den = 0.f;

    int e = e0;
    for (; e + 2 <= e1; e += 2) {
        int sA = g_esrc[e], sB = g_esrc[e + 1];
        float exA = g_ex[(size_t)e * HH + head];
        float exB = g_ex[(size_t)(e + 1) * HH + head];
        float4 aA = *(const float4*)(g_xl + (size_t)sA * HC + cb);
        float4 bA = *(const float4*)(g_xl + (size_t)sA * HC + cb + 4);
        float4 aB = *(const float4*)(g_xl + (size_t)sB * HC + cb);
        float4 bB = *(const float4*)(g_xl + (size_t)sB * HC + cb + 4);
        ull eA = dup2(exA), eB = dup2(exB);
        acc0 = fma2(pk2(aA.x, aA.y), eA, acc0);
        acc1 = fma2(pk2(aA.z, aA.w), eA, acc1);
        acc2 = fma2(pk2(bA.x, bA.y), eA, acc2);
        acc3 = fma2(pk2(bA.z, bA.w), eA, acc3);
        acc0 = fma2(pk2(aB.x, aB.y), eB, acc0);
        acc1 = fma2(pk2(aB.z, aB.w), eB, acc1);
        acc2 = fma2(pk2(bB.x, bB.y), eB, acc2);
        acc3 = fma2(pk2(bB.z, bB.w), eB, acc3);
        den += exA + exB;
    }
    if (e < e1) {
        int sA = g_esrc[e];
        float exA = g_ex[(size_t)e * HH + head];
        float4 aA = *(const float4*)(g_xl + (size_t)sA * HC + cb);
        float4 bA = *(const float4*)(g_xl + (size_t)sA * HC + cb + 4);
        ull eA = dup2(exA);
        acc0 = fma2(pk2(aA.x, aA.y), eA, acc0);
        acc1 = fma2(pk2(aA.z, aA.w), eA, acc1);
        acc2 = fma2(pk2(bA.x, bA.y), eA, acc2);
        acc3 = fma2(pk2(bA.z, bA.w), eA, acc3);
        den += exA;
    }

    float inv = 1.f / (den + 1e-16f);
    float r[8];
    {
        float2 f0 = up2(acc0), f1 = up2(acc1), f2 = up2(acc2), f3 = up2(acc3);
        r[0] = f0.x * inv; r[1] = f0.y * inv; r[2] = f1.x * inv; r[3] = f1.y * inv;
        r[4] = f2.x * inv; r[5] = f2.y * inv; r[6] = f3.x * inv; r[7] = f3.y * inv;
    }
    // head mean: lanes l, l^8, l^16, l^24 hold same within-head channels
    float4 bi0 = *(const float4*)(bias + wc);
    float4 bi1 = *(const float4*)(bias + wc + 4);
#pragma unroll
    for (int i = 0; i < 8; i++) {
        r[i] += __shfl_xor_sync(0xffffffffu, r[i], 8);
        r[i] += __shfl_xor_sync(0xffffffffu, r[i], 16);
    }
    r[0] = 0.25f * r[0] + bi0.x; r[1] = 0.25f * r[1] + bi0.y;
    r[2] = 0.25f * r[2] + bi0.z; r[3] = 0.25f * r[3] + bi0.w;
    r[4] = 0.25f * r[4] + bi1.x; r[5] = 0.25f * r[5] + bi1.y;
    r[6] = 0.25f * r[6] + bi1.z; r[7] = 0.25f * r[7] + bi1.w;

    // LayerNorm over 64 channels (each 8-lane group holds a full replica)
    float m = 0.f;
#pragma unroll
    for (int i = 0; i < 8; i++) m += r[i];
    m += __shfl_xor_sync(0xffffffffu, m, 1);
    m += __shfl_xor_sync(0xffffffffu, m, 2);
    m += __shfl_xor_sync(0xffffffffu, m, 4);
    m *= (1.f / 64.f);
    float v = 0.f;
#pragma unroll
    for (int i = 0; i < 8; i++) { float dd = r[i] - m; v = fmaf(dd, dd, v); }
    v += __shfl_xor_sync(0xffffffffu, v, 1);
    v += __shfl_xor_sync(0xffffffffu, v, 2);
    v += __shfl_xor_sync(0xffffffffu, v, 4);
    v *= (1.f / 64.f);
    float rstd = rsqrtf(v + 1e-5f);

    if (lane < 8) {
        float4 lg0 = *(const float4*)(lng + wc);
        float4 lg1 = *(const float4*)(lng + wc + 4);
        float4 lb0 = *(const float4*)(lnb + wc);
        float4 lb1 = *(const float4*)(lnb + wc + 4);
        float y[8];
        y[0] = (r[0] - m) * rstd * lg0.x + lb0.x;
        y[1] = (r[1] - m) * rstd * lg0.y + lb0.y;
        y[2] = (r[2] - m) * rstd * lg0.z + lb0.z;
        y[3] = (r[3] - m) * rstd * lg0.w + lb0.w;
        y[4] = (r[4] - m) * rstd * lg1.x + lb1.x;
        y[5] = (r[5] - m) * rstd * lg1.y + lb1.y;
        y[6] = (r[6] - m) * rstd * lg1.z + lb1.z;
        y[7] = (r[7] - m) * rstd * lg1.w + lb1.w;
        if (residual) {
            float4 rs0 = *(const float4*)(residual + (size_t)n * DD + wc);
            float4 rs1 = *(const float4*)(residual + (size_t)n * DD + wc + 4);
            y[0] += rs0.x; y[1] += rs0.y; y[2] += rs0.z; y[3] += rs0.w;
            y[4] += rs1.x; y[5] += rs1.y; y[6] += rs1.z; y[7] += rs1.w;
        }
        const float ks = 0.70710678118654752f;
        float o[8];
#pragma unroll
        for (int i = 0; i < 8; i++)
            o[i] = 0.5f * y[i] * (1.f + erff(y[i] * ks));
        float4* op = (float4*)(out + (size_t)n * DD + wc);
        op[0] = make_float4(o[0], o[1], o[2], o[3]);
        op[1] = make_float4(o[4], o[5], o[6], o[7]);
    }
}

// ---------------- launch ----------------
extern "C" void kernel_launch(void* const* d_in, const int* in_sizes, int n_in,
                              void* d_out, int out_size) {
    const float* h      = (const float*)d_in[0];
    const int*   ei     = (const int*)d_in[1];
    const float* ea     = (const float*)d_in[2];
    const float* g1_Wl  = (const float*)d_in[3];
    const float* g1_bl  = (const float*)d_in[4];
    const float* g1_Wr  = (const float*)d_in[5];
    const float* g1_br  = (const float*)d_in[6];
    const float* g1_We  = (const float*)d_in[7];
    const float* g1_att = (const float*)d_in[8];
    const float* g1_bias= (const float*)d_in[9];
    const float* ln1_g  = (const float*)d_in[10];
    const float* ln1_b  = (const float*)d_in[11];
    const float* g2_Wl  = (const float*)d_in[12];
    const float* g2_bl  = (const float*)d_in[13];
    const float* g2_Wr  = (const float*)d_in[14];
    const float* g2_br  = (const float*)d_in[15];
    const float* g2_We  = (const float*)d_in[16];
    const float* g2_att = (const float*)d_in[17];
    const float* g2_bias= (const float*)d_in[18];
    const float* ln2_g  = (const float*)d_in[19];
    const float* ln2_b  = (const float*)d_in[20];
    float* out = (float*)d_out;

    const int* src = ei;
    const int* dst = ei + EE;

    zero_cnt_kernel<<<(NN + 255) / 256, 256>>>();
    hist_kernel<<<(EE + 255) / 256, 256>>>(dst);
    scan_kernel<<<1, 1024>>>();
    scatter_kernel<<<(EE + 255) / 256, 256>>>(src, dst);
    permute_ea_kernel<<<(EE * 4 + 255) / 256, 256>>>(ea);

    // layer 1
    transform_kernel<<<(NN + 63) / 64, 512>>>(h, g1_Wl, g1_bl, g1_Wr, g1_br);
    alpha_kernel<<<EE / 64, 256>>>(g1_We, g1_att);
    agg_kernel<<<(NN * 32 + 255) / 256, 256>>>(g1_bias, ln1_g, ln1_b,
                                               nullptr, nullptr, 0);
    // layer 2
    transform_kernel<<<(NN + 63) / 64, 512>>>(nullptr, g2_Wl, g2_bl, g2_Wr, g2_br);
    alpha_kernel<<<EE / 64, 256>>>(g2_We, g2_att);
    agg_kernel<<<(NN * 32 + 255) / 256, 256>>>(g2_bias, ln2_g, ln2_b,
                                               h, out, 1);
}